// round 14
// baseline (speedup 1.0000x reference)
#include <cuda_runtime.h>
#include <cuda_fp16.h>
#include <math.h>
#include <stdint.h>

#define SS 512   // seq len
#define BB 64    // batch
#define HH 512   // hidden
#define II 512   // input

// ---------------- device scratch (no allocs allowed) ----------------
__device__ __half g_x16[BB * SS][II];        // fp16 copy of x, 33.5 MB
__device__ __half g_w16[8][HH][II];          // W transposed [z][n][k], 4.2 MB
__device__ __half g_xw16[8][BB * SS][HH];    // xw fp16, 268 MB

// ---------------- PTX helpers ----------------
__device__ __forceinline__ void mma16816(float* c, const unsigned* a, const unsigned* b) {
    asm volatile(
        "mma.sync.aligned.m16n8k16.row.col.f32.f16.f16.f32 "
        "{%0,%1,%2,%3}, {%4,%5,%6,%7}, {%8,%9}, {%0,%1,%2,%3};\n"
        : "+f"(c[0]), "+f"(c[1]), "+f"(c[2]), "+f"(c[3])
        : "r"(a[0]), "r"(a[1]), "r"(a[2]), "r"(a[3]), "r"(b[0]), "r"(b[1]));
}
__device__ __forceinline__ void ldmx4(unsigned* a, const void* p) {
    unsigned addr = (unsigned)__cvta_generic_to_shared(p);
    asm volatile("ldmatrix.sync.aligned.m8n8.x4.shared.b16 {%0,%1,%2,%3}, [%4];"
                 : "=r"(a[0]), "=r"(a[1]), "=r"(a[2]), "=r"(a[3]) : "r"(addr));
}
__device__ __forceinline__ void cpa16(void* s, const void* g) {
    unsigned sa = (unsigned)__cvta_generic_to_shared(s);
    asm volatile("cp.async.cg.shared.global [%0], [%1], 16;" :: "r"(sa), "l"(g));
}
#define CP_COMMIT() asm volatile("cp.async.commit_group;")
#define CP_WAIT(n)  asm volatile("cp.async.wait_group %0;" :: "n"(n))

__device__ __forceinline__ uint32_t smem_u32(const void* p) {
    return (uint32_t)__cvta_generic_to_shared(p);
}
__device__ __forceinline__ float tanhap(float x) {
    float y; asm("tanh.approx.f32 %0, %1;" : "=f"(y) : "f"(x)); return y;
}
__device__ __forceinline__ float sig_fast(float x) {
    return fmaf(0.5f, tanhap(0.5f * x), 0.5f);
}

#define CLUSTER_ARRIVE() asm volatile("barrier.cluster.arrive.aligned;" ::: "memory")
#define CLUSTER_WAIT()   asm volatile("barrier.cluster.wait.aligned;" ::: "memory")

// ---------------- converts ----------------
__global__ __launch_bounds__(256) void cvt_x_kernel(const float* __restrict__ x) {
    int i4 = blockIdx.x * 256 + threadIdx.x;
    float4 v = *(const float4*)&x[(size_t)i4 * 4];
    __half2* dst = (__half2*)&g_x16[0][0];
    dst[i4 * 2]     = __floats2half2_rn(v.x, v.y);
    dst[i4 * 2 + 1] = __floats2half2_rn(v.z, v.w);
}

__global__ __launch_bounds__(256) void cvt_w_kernel(
    const float* __restrict__ Wf, const float* __restrict__ Wb) {
    const int z = blockIdx.z;
    const float* W = (z < 4 ? Wf : Wb) + (size_t)(z & 3) * II * HH;
    __shared__ float t[32][33];
    const int tx = threadIdx.x & 31, ty = threadIdx.x >> 5;
    const int k0 = blockIdx.y * 32, n0 = blockIdx.x * 32;
    #pragma unroll
    for (int i = 0; i < 4; i++)
        t[ty + 8 * i][tx] = W[(size_t)(k0 + ty + 8 * i) * HH + n0 + tx];
    __syncthreads();
    #pragma unroll
    for (int i = 0; i < 4; i++)
        g_w16[z][n0 + ty + 8 * i][k0 + tx] = __float2half_rn(t[tx][ty + 8 * i]);
}

// ---------------- phase 1: input projection GEMM (R8 config: 128x64, 2-stage) ----------------
__global__ __launch_bounds__(256) void proj_kernel(
    const float* __restrict__ bf, const float* __restrict__ bb)
{
    const int z = blockIdx.z;
    const float* bias = (z < 4 ? bf : bb) + (z & 3) * HH;
    const int m0 = blockIdx.x * 128;
    const int n0 = blockIdx.y * 64;

    extern __shared__ __align__(16) __half psm[];
    __half* As = psm;                 // [2][128][72]
    __half* Bs = psm + 2 * 128 * 72;  // [2][64][72]

    const int tid  = threadIdx.x;
    const int lane = tid & 31;
    const int wid  = tid >> 5;
    const int wm   = wid & 3;
    const int wn   = wid >> 2;
    const int arow = (lane & 7) | (((lane >> 3) & 1) << 3);
    const int acol = (lane >> 4) << 3;

    float acc[2][4][4];
    #pragma unroll
    for (int i = 0; i < 2; i++)
        #pragma unroll
        for (int jj = 0; jj < 4; jj++)
            #pragma unroll
            for (int q = 0; q < 4; q++) acc[i][jj][q] = 0.f;

    auto issue = [&](int st, int kc) {
        __half* a = As + st * 128 * 72;
        __half* b = Bs + st * 64 * 72;
        #pragma unroll
        for (int w = 0; w < 4; w++) {
            int f = tid + w * 256;
            int row = f >> 3, u = f & 7;
            cpa16(&a[row * 72 + u * 8], &g_x16[m0 + row][kc + u * 8]);
        }
        #pragma unroll
        for (int w = 0; w < 2; w++) {
            int f = tid + w * 256;
            int row = f >> 3, u = f & 7;
            cpa16(&b[row * 72 + u * 8], &g_w16[z][n0 + row][kc + u * 8]);
        }
        CP_COMMIT();
    };

    issue(0, 0);
    for (int kb = 0; kb < 8; kb++) {
        const int cur = kb & 1;
        if (kb < 7) { issue(cur ^ 1, (kb + 1) * 64); CP_WAIT(1); }
        else        { CP_WAIT(0); }
        __syncthreads();
        const __half* a0 = As + cur * 128 * 72;
        const __half* b0 = Bs + cur * 64 * 72;
        #pragma unroll
        for (int k16 = 0; k16 < 4; k16++) {
            unsigned a[2][4], b[4][2];
            #pragma unroll
            for (int mt = 0; mt < 2; mt++)
                ldmx4(a[mt], &a0[(wm * 32 + mt * 16 + arow) * 72 + k16 * 16 + acol]);
            #pragma unroll
            for (int nt = 0; nt < 4; nt++) {
                const __half* bp = &b0[(wn * 32 + nt * 8 + (lane >> 2)) * 72 + k16 * 16 + ((lane & 3) << 1)];
                b[nt][0] = *(const unsigned*)bp;
                b[nt][1] = *(const unsigned*)(bp + 8);
            }
            #pragma unroll
            for (int mt = 0; mt < 2; mt++)
                #pragma unroll
                for (int nt = 0; nt < 4; nt++)
                    mma16816(acc[mt][nt], a[mt], b[nt]);
        }
        __syncthreads();
    }

    #pragma unroll
    for (int mt = 0; mt < 2; mt++) {
        #pragma unroll
        for (int nt = 0; nt < 4; nt++) {
            int n = n0 + wn * 32 + nt * 8 + ((lane & 3) << 1);
            float bx = bias[n], by = bias[n + 1];
            int mA = m0 + wm * 32 + mt * 16 + (lane >> 2);
            *(__half2*)&g_xw16[z][mA][n]     = __floats2half2_rn(acc[mt][nt][0] + bx, acc[mt][nt][1] + by);
            *(__half2*)&g_xw16[z][mA + 8][n] = __floats2half2_rn(acc[mt][nt][2] + bx, acc[mt][nt][3] + by);
        }
    }
}

// ---------------- phase 2: persistent recurrent kernel (16-CTA clusters, DSMEM) ----------------
// 128 CTAs = 8 clusters of 16. dir = bid>>6, bblk = (bid>>4)&3, hblk = bid&15 (= cluster rank).
// Each CTA holds a double-buffered 16 KB h image (swizzled for ldmatrix). After pointwise,
// each CTA pushes its 1 KB slice into all 16 cluster peers' next-buffer image via
// mapa + st.shared::cluster. One HW cluster barrier per step.
#define LSM_AS0  0
#define LSM_AS1  16384
#define LSM_US   32768
#define LSM_PRE  (LSM_US + 128 * 520 * 2)        // 165,888
#define LSM_STG  (LSM_PRE + 4 * 16 * 34 * 4)     // 174,592
#define LSM_TOT  (LSM_STG + 1024)                // 175,616

__global__ void __launch_bounds__(256, 1) __cluster_dims__(16, 1, 1)
lstm_kernel(const float* __restrict__ Uf, const float* __restrict__ Ub,
            float* __restrict__ out)
{
    const int bid  = blockIdx.x;
    const int dir  = bid >> 6;
    const int bblk = (bid >> 4) & 3;
    const int hblk = bid & 15;              // == cluster rank
    const int b0   = bblk * 16;
    const int h0g  = hblk * 32;

    extern __shared__ __align__(1024) char smraw[];
    const uint32_t smem_base = smem_u32(smraw);
    __half* Us   = (__half*)(smraw + LSM_US);   // [128][520] col c = g*32+jj
    float*  pre  = (float*)(smraw + LSM_PRE);   // [4][16][34]
    char*   stg  = smraw + LSM_STG;             // [16][64B] own-slice staging

    const int tid  = threadIdx.x;
    const int lane = tid & 31;
    const int wid  = tid >> 5;                  // n-tile id 0..7
    const int lrow = (lane & 15);
    const int lcol = (lane >> 4) << 3;
    const int a_row_byte = lrow * 1024;
    const int a_sw       = (lrow & 7) << 4;

    const int pb = tid >> 4;            // 0..15 local batch
    const int pj = (tid & 15) << 1;     // 0..30 local h col pair

    const float* U = dir ? Ub : Uf;     // [4][HH][HH]

    // U slice -> fp16 smem
    for (int idx = tid; idx < 128 * 512; idx += 256) {
        int c = idx & 127, k = idx >> 7;
        Us[c * 520 + k] = __float2half_rn(U[((size_t)(c >> 5) * HH + k) * HH + h0g + (c & 31)]);
    }
    // zero own As0 image (h_0 = 0)
    {
        float4 z = make_float4(0.f, 0.f, 0.f, 0.f);
        #pragma unroll
        for (int w = 0; w < 4; w++)
            *(float4*)(smraw + LSM_AS0 + (tid + w * 256) * 16) = z;
    }
    __syncthreads();
    CLUSTER_ARRIVE();

    float creg[2] = {0.f, 0.f};
    float2 xr[4];
    {
        const int s0 = dir ? (SS - 1) : 0;
        #pragma unroll
        for (int g2 = 0; g2 < 4; g2++)
            xr[g2] = __half22float2(*(const __half2*)&g_xw16[dir * 4 + g2][(size_t)(b0 + pb) * 512 + s0][h0g + pj]);
    }
    CLUSTER_WAIT();

    for (int t = 0; t < SS; t++) {
        const int s = dir ? (SS - 1 - t) : t;
        char* Asb = smraw + ((t & 1) ? LSM_AS1 : LSM_AS0);

        // ---- GEMM: preact[16b x 128] = h[16x512] @ Uslice ----
        float acc[2][4];
        #pragma unroll
        for (int a2 = 0; a2 < 2; a2++)
            #pragma unroll
            for (int q = 0; q < 4; q++) acc[a2][q] = 0.f;

        #pragma unroll
        for (int k16 = 0; k16 < 32; k16++) {
            const int k0 = k16 * 16;
            unsigned a[4], bbm[4];
            ldmx4(a, Asb + a_row_byte + (((k0 + lcol) * 2) ^ a_sw));
            ldmx4(bbm, &Us[(wid * 16 + lrow) * 520 + k0 + lcol]);
            unsigned bA[2] = { bbm[0], bbm[2] };
            unsigned bB[2] = { bbm[1], bbm[3] };
            mma16816(acc[0], a, bA);
            mma16816(acc[1], a, bB);
        }

        // ---- gate exchange ----
        #pragma unroll
        for (int nt = 0; nt < 2; nt++) {
            int c = wid * 16 + nt * 8 + ((lane & 3) << 1);
            int g = c >> 5, jj = c & 31;
            int r = lane >> 2;
            *(float2*)&pre[(g * 16 + r) * 34 + jj]     = make_float2(acc[nt][0], acc[nt][1]);
            *(float2*)&pre[(g * 16 + r + 8) * 34 + jj] = make_float2(acc[nt][2], acc[nt][3]);
        }
        __syncthreads();

        // ---- pointwise LSTM cell (gate order f,g,i,o) ----
        float hn[2];
        #pragma unroll
        for (int q = 0; q < 2; q++) {
            float pf = pre[(0 * 16 + pb) * 34 + pj + q] + (q ? xr[0].y : xr[0].x);
            float pg = pre[(1 * 16 + pb) * 34 + pj + q] + (q ? xr[1].y : xr[1].x);
            float pi = pre[(2 * 16 + pb) * 34 + pj + q] + (q ? xr[2].y : xr[2].x);
            float po = pre[(3 * 16 + pb) * 34 + pj + q] + (q ? xr[3].y : xr[3].x);
            float f = sig_fast(pf);
            float g = tanhap(pg);
            float i = sig_fast(pi);
            float o = sig_fast(po);
            creg[q] = creg[q] * f + g * i;
            hn[q] = o * tanhap(creg[q]);
        }
        // stage own slice [16 rows][64 B] in plain layout
        *(__half2*)(stg + pb * 64 + pj * 2) = __floats2half2_rn(hn[0], hn[1]);
        __syncthreads();

        // ---- DSMEM broadcast: own 1 KB slice -> all 16 peers' next As image ----
        {
            const uint32_t dstbase = smem_base + (((t + 1) & 1) ? LSM_AS1 : LSM_AS0);
            const int unit = tid & 63;          // b = unit>>2, u = unit&3
            const int ub = unit >> 2, uu = unit & 3;
            float4 v = *(float4*)(stg + unit * 16);
            const uint32_t dstoff = dstbase
                + (uint32_t)(ub * 1024 + ((h0g * 2 + uu * 16) ^ ((ub & 7) << 4)));
            #pragma unroll
            for (int k = 0; k < 4; k++) {
                uint32_t rank = (uint32_t)(tid >> 6) + k * 4u;   // 0..15
                uint32_t raddr;
                asm("mapa.shared::cluster.u32 %0, %1, %2;"
                    : "=r"(raddr) : "r"(dstoff), "r"(rank));
                asm volatile("st.shared::cluster.v4.b32 [%0], {%1, %2, %3, %4};"
                             :: "r"(raddr),
                                "r"(__float_as_uint(v.x)), "r"(__float_as_uint(v.y)),
                                "r"(__float_as_uint(v.z)), "r"(__float_as_uint(v.w))
                             : "memory");
            }
        }
        CLUSTER_ARRIVE();   // release: orders the remote stores

        // overlapped with peers' arrival: out store + next xw prefetch
        *(float2*)&out[(size_t)((s << 6) + b0 + pb) * 1024 + dir * HH + h0g + pj] = make_float2(hn[0], hn[1]);
        if (t + 1 < SS) {
            const int sn = dir ? (SS - 2 - t) : (t + 1);
            #pragma unroll
            for (int g2 = 0; g2 < 4; g2++)
                xr[g2] = __half22float2(*(const __half2*)&g_xw16[dir * 4 + g2][(size_t)(b0 + pb) * 512 + sn][h0g + pj]);
        }

        CLUSTER_WAIT();
    }
}

// ---------------- phase 3: finalize h_f / h_b from mask ----------------
__global__ void final_kernel(const unsigned char* __restrict__ mask,
                             float* __restrict__ out)
{
    const int b = blockIdx.x;
    const int tid = threadIdx.x;

    __shared__ int mode;
    if (tid == 0)
        mode = (mask[0] == 1 && mask[1] == 0 && mask[2] == 0 && mask[3] == 0) ? 1 : 0;
    __syncthreads();

    int v;
    if (mode) {
        const int* mi = (const int*)mask;
        v = (mi[b * SS + tid] != 0) ? 1 : 0;
    } else {
        v = (mask[b * SS + tid] != 0) ? 1 : 0;
    }
    int len = __syncthreads_count(v);
    int idx = (len > 0) ? (len - 1) : 0;

    float* hf = out + (size_t)SS * BB * 1024;
    float* hb = hf + (size_t)BB * HH;
    hf[b * HH + tid] = out[(size_t)((idx << 6) + b) * 1024 + tid];
    hb[b * HH + tid] = out[(size_t)b * 1024 + HH + tid];
}

// ---------------- launch ----------------
extern "C" void kernel_launch(void* const* d_in, const int* in_sizes, int n_in,
                              void* d_out, int out_size)
{
    const float* x  = (const float*)d_in[0];
    const unsigned char* mask = (const unsigned char*)d_in[1];
    const float* Uf = (const float*)d_in[2];
    const float* Wf = (const float*)d_in[3];
    const float* bf = (const float*)d_in[4];
    const float* Ub = (const float*)d_in[5];
    const float* Wb = (const float*)d_in[6];
    const float* bb = (const float*)d_in[7];
    float* out = (float*)d_out;

    cvt_x_kernel<<<BB * SS * II / 4 / 256, 256>>>(x);
    dim3 wg(16, 16, 8);
    cvt_w_kernel<<<wg, 256>>>(Wf, Wb);

    size_t psmem = (size_t)(2 * 128 * 72 + 2 * 64 * 72) * sizeof(__half);  // 55,296 B
    cudaFuncSetAttribute(proj_kernel, cudaFuncAttributeMaxDynamicSharedMemorySize, (int)psmem);
    dim3 pg(BB * SS / 128, HH / 64, 8);   // (256, 8, 8)
    proj_kernel<<<pg, 256, psmem>>>(bf, bb);

    cudaFuncSetAttribute(lstm_kernel, cudaFuncAttributeMaxDynamicSharedMemorySize, LSM_TOT);
    cudaFuncSetAttribute(lstm_kernel, cudaFuncAttributeNonPortableClusterSizeAllowed, 1);
    lstm_kernel<<<128, 256, LSM_TOT>>>(Uf, Ub, out);

    final_kernel<<<BB, SS>>>(mask, out);
}

// round 15
// speedup vs baseline: 1.5625x; 1.5625x over previous
#include <cuda_runtime.h>
#include <cuda_fp16.h>
#include <math.h>
#include <stdint.h>

#define SS 512   // seq len
#define BB 64    // batch
#define HH 512   // hidden
#define II 512   // input
#define NGRP 32  // CTAs per barrier group (one b-block, one dir)

// ---------------- device scratch (no allocs allowed) ----------------
__device__ __half g_x16[BB * SS][II];        // fp16 copy of x, 33.5 MB
__device__ __half g_w16[8][HH][II];          // W transposed [z][n][k], 4.2 MB
__device__ __half g_xw16[8][BB * SS][HH];    // xw fp16, 268 MB
// h double buffer; within each 16-batch block rows are stored with byte
// swizzle (2k)^((b&7)<<4) so a raw bulk-copy into SMEM is ldmatrix-conflict-free
__device__ __align__(1024) __half g_h16[2][2][BB][HH];
__device__ unsigned int g_flag[2][128][8];   // per-CTA progress flags, 32B padded

// ---------------- PTX helpers ----------------
__device__ __forceinline__ void mma16816(float* c, const unsigned* a, const unsigned* b) {
    asm volatile(
        "mma.sync.aligned.m16n8k16.row.col.f32.f16.f16.f32 "
        "{%0,%1,%2,%3}, {%4,%5,%6,%7}, {%8,%9}, {%0,%1,%2,%3};\n"
        : "+f"(c[0]), "+f"(c[1]), "+f"(c[2]), "+f"(c[3])
        : "r"(a[0]), "r"(a[1]), "r"(a[2]), "r"(a[3]), "r"(b[0]), "r"(b[1]));
}
__device__ __forceinline__ void ldmx4(unsigned* a, const void* p) {
    unsigned addr = (unsigned)__cvta_generic_to_shared(p);
    asm volatile("ldmatrix.sync.aligned.m8n8.x4.shared.b16 {%0,%1,%2,%3}, [%4];"
                 : "=r"(a[0]), "=r"(a[1]), "=r"(a[2]), "=r"(a[3]) : "r"(addr));
}
__device__ __forceinline__ void cpa16(void* s, const void* g) {
    unsigned sa = (unsigned)__cvta_generic_to_shared(s);
    asm volatile("cp.async.cg.shared.global [%0], [%1], 16;" :: "r"(sa), "l"(g));
}
#define CP_COMMIT() asm volatile("cp.async.commit_group;")
#define CP_WAIT(n)  asm volatile("cp.async.wait_group %0;" :: "n"(n))

__device__ __forceinline__ uint32_t smem_u32(const void* p) {
    return (uint32_t)__cvta_generic_to_shared(p);
}
__device__ __forceinline__ float tanhap(float x) {
    float y; asm("tanh.approx.f32 %0, %1;" : "=f"(y) : "f"(x)); return y;
}
__device__ __forceinline__ float sig_fast(float x) {
    return fmaf(0.5f, tanhap(0.5f * x), 0.5f);
}

// ---------------- bulk copy + mbarrier ----------------
#define MBARRIER_INIT(mbar, cnt) \
    asm volatile("mbarrier.init.shared.b64 [%0], %1;" :: "r"((uint32_t)(mbar)), "r"((uint32_t)(cnt)) : "memory")
#define MBARRIER_EXPECT_TX(mbar, bytes) \
    asm volatile("mbarrier.arrive.expect_tx.shared.b64 _, [%0], %1;" \
                 :: "r"((uint32_t)(mbar)), "r"((uint32_t)(bytes)) : "memory")
#define FENCE_PROXY_ASYNC() asm volatile("fence.proxy.async.shared::cta;" ::: "memory")

__device__ __forceinline__ void bulk_ld(uint32_t smem_dst, const void* gsrc,
                                        uint32_t bytes, uint32_t mbar) {
    asm volatile(
        "cp.async.bulk.shared::cluster.global.mbarrier::complete_tx::bytes [%0], [%1], %2, [%3];"
        :: "r"(smem_dst), "l"(gsrc), "r"(bytes), "r"(mbar) : "memory");
}
__device__ __forceinline__ void mbar_wait(uint32_t mbar, uint32_t parity) {
    asm volatile(
        "{\n\t.reg .pred P;\n\t"
        "LW%=:\n\t"
        "mbarrier.try_wait.parity.acquire.cta.shared::cta.b64 P, [%0], %1, 0x989680;\n\t"
        "@!P bra LW%=;\n\t}"
        :: "r"(mbar), "r"(parity) : "memory");
}

// ---------------- flag barrier ----------------
__device__ __forceinline__ void flag_publish(int dir, int slice, unsigned gen) {
    if (threadIdx.x == 0)
        asm volatile("st.release.gpu.global.u32 [%0], %1;"
                     :: "l"(&g_flag[dir][slice][0]), "r"(gen) : "memory");
}
__device__ __forceinline__ void flag_wait_group(int dir, int gbase, unsigned gen) {
    if (threadIdx.x < NGRP) {
        const unsigned* p = &g_flag[dir][gbase + threadIdx.x][0];
        unsigned v;
        do {
            asm volatile("ld.acquire.gpu.global.u32 %0, [%1];"
                         : "=r"(v) : "l"(p) : "memory");
        } while (v < gen);
    }
    __syncthreads();
}

// ---------------- init ----------------
__global__ void init_kernel() {
    unsigned* p = &g_flag[0][0][0];
    for (int i = threadIdx.x; i < 2 * 128 * 8; i += blockDim.x) p[i] = 0;
}

// ---------------- converts ----------------
__global__ __launch_bounds__(256) void cvt_x_kernel(const float* __restrict__ x) {
    int i4 = blockIdx.x * 256 + threadIdx.x;
    float4 v = *(const float4*)&x[(size_t)i4 * 4];
    __half2* dst = (__half2*)&g_x16[0][0];
    dst[i4 * 2]     = __floats2half2_rn(v.x, v.y);
    dst[i4 * 2 + 1] = __floats2half2_rn(v.z, v.w);
}

__global__ __launch_bounds__(256) void cvt_w_kernel(
    const float* __restrict__ Wf, const float* __restrict__ Wb) {
    const int z = blockIdx.z;
    const float* W = (z < 4 ? Wf : Wb) + (size_t)(z & 3) * II * HH;
    __shared__ float t[32][33];
    const int tx = threadIdx.x & 31, ty = threadIdx.x >> 5;
    const int k0 = blockIdx.y * 32, n0 = blockIdx.x * 32;
    #pragma unroll
    for (int i = 0; i < 4; i++)
        t[ty + 8 * i][tx] = W[(size_t)(k0 + ty + 8 * i) * HH + n0 + tx];
    __syncthreads();
    #pragma unroll
    for (int i = 0; i < 4; i++)
        g_w16[z][n0 + ty + 8 * i][k0 + tx] = __float2half_rn(t[tx][ty + 8 * i]);
}

// ---------------- phase 1: input projection GEMM (R8 config: 128x64, 2-stage) ----------------
__global__ __launch_bounds__(256) void proj_kernel(
    const float* __restrict__ bf, const float* __restrict__ bb)
{
    const int z = blockIdx.z;
    const float* bias = (z < 4 ? bf : bb) + (z & 3) * HH;
    const int m0 = blockIdx.x * 128;
    const int n0 = blockIdx.y * 64;

    extern __shared__ __align__(16) __half psm[];
    __half* As = psm;                 // [2][128][72]
    __half* Bs = psm + 2 * 128 * 72;  // [2][64][72]

    const int tid  = threadIdx.x;
    const int lane = tid & 31;
    const int wid  = tid >> 5;
    const int wm   = wid & 3;
    const int wn   = wid >> 2;
    const int arow = (lane & 7) | (((lane >> 3) & 1) << 3);
    const int acol = (lane >> 4) << 3;

    float acc[2][4][4];
    #pragma unroll
    for (int i = 0; i < 2; i++)
        #pragma unroll
        for (int jj = 0; jj < 4; jj++)
            #pragma unroll
            for (int q = 0; q < 4; q++) acc[i][jj][q] = 0.f;

    auto issue = [&](int st, int kc) {
        __half* a = As + st * 128 * 72;
        __half* b = Bs + st * 64 * 72;
        #pragma unroll
        for (int w = 0; w < 4; w++) {
            int f = tid + w * 256;
            int row = f >> 3, u = f & 7;
            cpa16(&a[row * 72 + u * 8], &g_x16[m0 + row][kc + u * 8]);
        }
        #pragma unroll
        for (int w = 0; w < 2; w++) {
            int f = tid + w * 256;
            int row = f >> 3, u = f & 7;
            cpa16(&b[row * 72 + u * 8], &g_w16[z][n0 + row][kc + u * 8]);
        }
        CP_COMMIT();
    };

    issue(0, 0);
    for (int kb = 0; kb < 8; kb++) {
        const int cur = kb & 1;
        if (kb < 7) { issue(cur ^ 1, (kb + 1) * 64); CP_WAIT(1); }
        else        { CP_WAIT(0); }
        __syncthreads();
        const __half* a0 = As + cur * 128 * 72;
        const __half* b0 = Bs + cur * 64 * 72;
        #pragma unroll
        for (int k16 = 0; k16 < 4; k16++) {
            unsigned a[2][4], b[4][2];
            #pragma unroll
            for (int mt = 0; mt < 2; mt++)
                ldmx4(a[mt], &a0[(wm * 32 + mt * 16 + arow) * 72 + k16 * 16 + acol]);
            #pragma unroll
            for (int nt = 0; nt < 4; nt++) {
                const __half* bp = &b0[(wn * 32 + nt * 8 + (lane >> 2)) * 72 + k16 * 16 + ((lane & 3) << 1)];
                b[nt][0] = *(const unsigned*)bp;
                b[nt][1] = *(const unsigned*)(bp + 8);
            }
            #pragma unroll
            for (int mt = 0; mt < 2; mt++)
                #pragma unroll
                for (int nt = 0; nt < 4; nt++)
                    mma16816(acc[mt][nt], a[mt], b[nt]);
        }
        __syncthreads();
    }

    #pragma unroll
    for (int mt = 0; mt < 2; mt++) {
        #pragma unroll
        for (int nt = 0; nt < 4; nt++) {
            int n = n0 + wn * 32 + nt * 8 + ((lane & 3) << 1);
            float bx = bias[n], by = bias[n + 1];
            int mA = m0 + wm * 32 + mt * 16 + (lane >> 2);
            *(__half2*)&g_xw16[z][mA][n]     = __floats2half2_rn(acc[mt][nt][0] + bx, acc[mt][nt][1] + by);
            *(__half2*)&g_xw16[z][mA + 8][n] = __floats2half2_rn(acc[mt][nt][2] + bx, acc[mt][nt][3] + by);
        }
    }
}

// ---------------- phase 2: persistent recurrent kernel (2 CTAs/SM) ----------------
// 256 CTAs x 128 threads, 2 per SM. dir = bid>>7, slice = bid&127;
// bblk = slice>>5 (16 batches), hslice = slice&31 (16 h-cols).
// Per CTA per step: preact[16b x 64(4g x 16h)] = h[16x512] @ Uslice[512x64].
// 4 warps of 16x16 n-tiles. Groups of 32 CTAs share a b-block; co-resident
// CTA pairs from different groups hide each other's sync/load latency.
#define LSM_AS   0
#define LSM_US   16384
#define LSM_PRE  (LSM_US + 64 * 520 * 2)         // 82,944
#define LSM_MBAR (LSM_PRE + 4 * 16 * 18 * 4)     // 87,552
#define LSM_TOT  (LSM_MBAR + 16)                 // 87,568

__global__ void __launch_bounds__(128, 2) lstm_kernel(
    const float* __restrict__ Uf, const float* __restrict__ Ub,
    float* __restrict__ out)
{
    const int bid    = blockIdx.x;
    const int dir    = bid >> 7;
    const int slice  = bid & 127;
    const int bblk   = slice >> 5;
    const int hslice = slice & 31;
    const int b0     = bblk * 16;
    const int h0g    = hslice * 16;
    const int gbase  = bblk * 32;

    extern __shared__ __align__(1024) char smraw[];
    char*   Asb = smraw + LSM_AS;              // [16][1024B] swizzled h tile
    __half* Us  = (__half*)(smraw + LSM_US);   // [64][520]  col c = g*16+jj
    float*  pre = (float*)(smraw + LSM_PRE);   // [4][16][18]
    const uint32_t as_s   = smem_u32(Asb);
    const uint32_t mbar_s = smem_u32(smraw + LSM_MBAR);

    const int tid  = threadIdx.x;
    const int lane = tid & 31;
    const int wid  = tid >> 5;                 // n-tile id 0..3
    const int lrow = (lane & 15);
    const int lcol = (lane >> 4) << 3;
    const int a_row_byte = lrow * 1024;
    const int a_sw       = (lrow & 7) << 4;

    const int pb = tid >> 3;            // 0..15 local batch
    const int pj = (tid & 7) << 1;      // 0..14 local h col pair

    const float* U = dir ? Ub : Uf;     // [4][HH][HH]

    // U slice -> fp16 smem: Us[c][k] = U[c>>4][k][h0g + (c&15)]
    for (int idx = tid; idx < 64 * 512; idx += 128) {
        int c = idx & 63, k = idx >> 6;
        Us[c * 520 + k] = __float2half_rn(U[((size_t)(c >> 4) * HH + k) * HH + h0g + (c & 15)]);
    }
    // zero own h slice in buffer 0 (16b x 16 cols; plain addressing is fine for zeros)
    *(__half2*)&g_h16[dir][0][b0 + pb][h0g + pj] = __floats2half2_rn(0.f, 0.f);
    if (tid == 0) MBARRIER_INIT(mbar_s, 1);

    float creg[2] = {0.f, 0.f};

    __syncthreads();
    flag_publish(dir, slice, 1u);

    float2 xr[4];
    {
        const int s0 = dir ? (SS - 1) : 0;
        #pragma unroll
        for (int g2 = 0; g2 < 4; g2++)
            xr[g2] = __half22float2(*(const __half2*)&g_xw16[dir * 4 + g2][(size_t)(b0 + pb) * 512 + s0][h0g + pj]);
    }

    flag_wait_group(dir, gbase, 1u);

    for (int t = 0; t < SS; t++) {
        const int s = dir ? (SS - 1 - t) : t;
        const char* hprev = (const char*)&g_h16[dir][t & 1][0][0];

        // ---- one bulk load of the 16 KB (pre-swizzled) h block ----
        if (tid == 0) {
            FENCE_PROXY_ASYNC();
            MBARRIER_EXPECT_TX(mbar_s, 16384u);
            bulk_ld(as_s, hprev + (size_t)b0 * 1024, 16384u, mbar_s);
        }
        mbar_wait(mbar_s, (uint32_t)(t & 1));

        // ---- GEMM: preact[16b x 64] = h[16x512] @ Uslice ----
        float acc[2][4];
        #pragma unroll
        for (int a2 = 0; a2 < 2; a2++)
            #pragma unroll
            for (int q = 0; q < 4; q++) acc[a2][q] = 0.f;

        #pragma unroll
        for (int k16 = 0; k16 < 32; k16++) {
            const int k0 = k16 * 16;
            unsigned a[4], bbm[4];
            ldmx4(a, Asb + a_row_byte + (((k0 + lcol) * 2) ^ a_sw));
            ldmx4(bbm, &Us[(wid * 16 + lrow) * 520 + k0 + lcol]);
            unsigned bA[2] = { bbm[0], bbm[2] };
            unsigned bB[2] = { bbm[1], bbm[3] };
            mma16816(acc[0], a, bA);
            mma16816(acc[1], a, bB);
        }

        // ---- gate exchange: c = wid*16 + nt*8 + (lane&3)*2; g = c>>4, jj = c&15 ----
        #pragma unroll
        for (int nt = 0; nt < 2; nt++) {
            int c = wid * 16 + nt * 8 + ((lane & 3) << 1);
            int g = c >> 4, jj = c & 15;
            int r = lane >> 2;
            *(float2*)&pre[(g * 16 + r) * 18 + jj]     = make_float2(acc[nt][0], acc[nt][1]);
            *(float2*)&pre[(g * 16 + r + 8) * 18 + jj] = make_float2(acc[nt][2], acc[nt][3]);
        }
        __syncthreads();

        // ---- pointwise LSTM cell (gate order f,g,i,o) ----
        char* hnext = (char*)&g_h16[dir][(t + 1) & 1][0][0];
        float hn[2];
        #pragma unroll
        for (int q = 0; q < 2; q++) {
            float pf = pre[(0 * 16 + pb) * 18 + pj + q] + (q ? xr[0].y : xr[0].x);
            float pg = pre[(1 * 16 + pb) * 18 + pj + q] + (q ? xr[1].y : xr[1].x);
            float pi = pre[(2 * 16 + pb) * 18 + pj + q] + (q ? xr[2].y : xr[2].x);
            float po = pre[(3 * 16 + pb) * 18 + pj + q] + (q ? xr[3].y : xr[3].x);
            float f = sig_fast(pf);
            float g = tanhap(pg);
            float i = sig_fast(pi);
            float o = sig_fast(po);
            creg[q] = creg[q] * f + g * i;
            hn[q] = o * tanhap(creg[q]);
        }
        // store with block swizzle: byte (2k)^((b&7)<<4) within the 16-row block
        {
            uint32_t off = (uint32_t)((b0 + pb) * 1024)
                         + ((uint32_t)((h0g + pj) * 2) ^ (uint32_t)((pb & 7) << 4));
            *(__half2*)(hnext + off) = __floats2half2_rn(hn[0], hn[1]);
        }

        __syncthreads();
        flag_publish(dir, slice, (unsigned)(t + 2));

        // overlapped with next wait: out store + next xw prefetch
        *(float2*)&out[(size_t)((s << 6) + b0 + pb) * 1024 + dir * HH + h0g + pj] = make_float2(hn[0], hn[1]);
        if (t + 1 < SS) {
            const int sn = dir ? (SS - 2 - t) : (t + 1);
            #pragma unroll
            for (int g2 = 0; g2 < 4; g2++)
                xr[g2] = __half22float2(*(const __half2*)&g_xw16[dir * 4 + g2][(size_t)(b0 + pb) * 512 + sn][h0g + pj]);
        }

        flag_wait_group(dir, gbase, (unsigned)(t + 2));
    }

    __syncthreads();
    if (tid == 0)
        asm volatile("mbarrier.inval.shared.b64 [%0];" :: "r"(mbar_s) : "memory");
}

// ---------------- phase 3: finalize h_f / h_b from mask ----------------
__global__ void final_kernel(const unsigned char* __restrict__ mask,
                             float* __restrict__ out)
{
    const int b = blockIdx.x;
    const int tid = threadIdx.x;

    __shared__ int mode;
    if (tid == 0)
        mode = (mask[0] == 1 && mask[1] == 0 && mask[2] == 0 && mask[3] == 0) ? 1 : 0;
    __syncthreads();

    int v;
    if (mode) {
        const int* mi = (const int*)mask;
        v = (mi[b * SS + tid] != 0) ? 1 : 0;
    } else {
        v = (mask[b * SS + tid] != 0) ? 1 : 0;
    }
    int len = __syncthreads_count(v);
    int idx = (len > 0) ? (len - 1) : 0;

    float* hf = out + (size_t)SS * BB * 1024;
    float* hb = hf + (size_t)BB * HH;
    hf[b * HH + tid] = out[(size_t)((idx << 6) + b) * 1024 + tid];
    hb[b * HH + tid] = out[(size_t)b * 1024 + HH + tid];
}

// ---------------- launch ----------------
extern "C" void kernel_launch(void* const* d_in, const int* in_sizes, int n_in,
                              void* d_out, int out_size)
{
    const float* x  = (const float*)d_in[0];
    const unsigned char* mask = (const unsigned char*)d_in[1];
    const float* Uf = (const float*)d_in[2];
    const float* Wf = (const float*)d_in[3];
    const float* bf = (const float*)d_in[4];
    const float* Ub = (const float*)d_in[5];
    const float* Wb = (const float*)d_in[6];
    const float* bb = (const float*)d_in[7];
    float* out = (float*)d_out;

    init_kernel<<<1, 256>>>();

    cvt_x_kernel<<<BB * SS * II / 4 / 256, 256>>>(x);
    dim3 wg(16, 16, 8);
    cvt_w_kernel<<<wg, 256>>>(Wf, Wb);

    size_t psmem = (size_t)(2 * 128 * 72 + 2 * 64 * 72) * sizeof(__half);  // 55,296 B
    cudaFuncSetAttribute(proj_kernel, cudaFuncAttributeMaxDynamicSharedMemorySize, (int)psmem);
    dim3 pg(BB * SS / 128, HH / 64, 8);   // (256, 8, 8)
    proj_kernel<<<pg, 256, psmem>>>(bf, bb);

    cudaFuncSetAttribute(lstm_kernel, cudaFuncAttributeMaxDynamicSharedMemorySize, LSM_TOT);
    lstm_kernel<<<256, 128, LSM_TOT>>>(Uf, Ub, out);

    final_kernel<<<BB, SS>>>(mask, out);
}